// round 1
// baseline (speedup 1.0000x reference)
#include <cuda_runtime.h>
#include <math.h>

#define T_TOK 2048
#define H_DIM 1024
#define NE    32
#define IDIM  512
#define K_TOP 6
#define ISH   1024
#define CAP   2048
#define NPAIR (T_TOK*K_TOP)   // 12288

// ---------------- scratch (static device globals; no runtime alloc) ----------
__device__ int   g_counts[NE];
__device__ int   g_offsets[NE];
__device__ int   g_bucket[NE*CAP];
__device__ int   g_topidx[NPAIR];
__device__ float g_topw[NPAIR];
__device__ int   g_slot[NPAIR];
__device__ float g_sg  [(size_t)T_TOK*ISH];
__device__ float g_su  [(size_t)T_TOK*ISH];
__device__ float g_smid[(size_t)T_TOK*ISH];
__device__ float g_gu  [(size_t)NPAIR*2*IDIM];
__device__ float g_hmid[(size_t)NPAIR*IDIM];
__device__ float g_y   [(size_t)NPAIR*H_DIM];

__device__ __forceinline__ float silu_f(float v){ return v / (1.f + __expf(-v)); }

// ---------------- router: softmax + bias + top-6 + bucketing ----------------
__global__ void zero_counts_kernel(){
    if (threadIdx.x < NE) g_counts[threadIdx.x] = 0;
}

__global__ void router_kernel(const float* __restrict__ x,
                              const float* __restrict__ rw,
                              const float* __restrict__ bias)
{
    __shared__ float sx[H_DIM];
    __shared__ float slog[NE];
    const int t = blockIdx.x;
    const float* xr = x + (size_t)t * H_DIM;
    for (int i = threadIdx.x; i < H_DIM; i += blockDim.x) sx[i] = xr[i];
    __syncthreads();

    const int warp = threadIdx.x >> 5, lane = threadIdx.x & 31;
    for (int e = warp*8; e < warp*8 + 8; e++){
        const float* w = rw + (size_t)e * H_DIM;
        float s = 0.f;
        for (int h = lane; h < H_DIM; h += 32) s += sx[h] * w[h];
        #pragma unroll
        for (int o = 16; o; o >>= 1) s += __shfl_xor_sync(0xffffffffu, s, o);
        if (lane == 0) slog[e] = s;
    }
    __syncthreads();

    if (threadIdx.x == 0){
        float mx = -1e30f;
        for (int e = 0; e < NE; e++) mx = fmaxf(mx, slog[e]);
        float p[NE]; float sum = 0.f;
        for (int e = 0; e < NE; e++){ p[e] = expf(slog[e] - mx); sum += p[e]; }
        float inv = 1.f / sum;
        float corr[NE];
        for (int e = 0; e < NE; e++){ p[e] *= inv; corr[e] = p[e] + bias[e]; }

        int idx[K_TOP]; bool used[NE];
        for (int e = 0; e < NE; e++) used[e] = false;
        for (int k = 0; k < K_TOP; k++){
            int best = -1; float bv = -1e30f;
            for (int e = 0; e < NE; e++)
                if (!used[e] && corr[e] > bv){ bv = corr[e]; best = e; }
            used[best] = true; idx[k] = best;
        }
        float wsum = 0.f;
        for (int k = 0; k < K_TOP; k++) wsum += p[idx[k]];
        wsum = fmaxf(wsum, 1e-12f);
        for (int k = 0; k < K_TOP; k++){
            int e = idx[k];
            float wn = p[e] / wsum;
            int slot = atomicAdd(&g_counts[e], 1);
            g_bucket[e*CAP + slot] = t;
            g_topidx[t*K_TOP + k] = e;
            g_topw [t*K_TOP + k] = wn;
            g_slot [t*K_TOP + k] = slot;
        }
    }
}

__global__ void scan_kernel(){
    if (threadIdx.x == 0){
        int s = 0;
        for (int e = 0; e < NE; e++){ g_offsets[e] = s; s += g_counts[e]; }
    }
}

// ---------------- SGEMM: C[m,n] = sum_k A[m,k]*B[n,k] (both K-contiguous) ----
// 128x128 tile, BK=8, 256 threads, 8x8 per thread (split 4+4 fragments for
// conflict-free LDS.128). A-load broadcast within 8-lane phases.

#define GEMM_PROLOG()                                                          \
    __shared__ float As[8][128];                                               \
    __shared__ float Bs[8][128];                                               \
    const int tid  = threadIdx.x;                                              \
    const int lr   = tid & 1, lrow = tid >> 1;                                 \
    const int warp = tid >> 5, lane = tid & 31;                                \
    const int wm = (warp >> 1) * 32, wn = (warp & 1) * 64;                     \
    const int lm = lane >> 3, ln = lane & 7;                                   \
    float acc[2][2][4][4];                                                     \
    _Pragma("unroll") for (int a=0;a<2;a++)                                    \
    _Pragma("unroll") for (int b=0;b<2;b++)                                    \
    _Pragma("unroll") for (int i=0;i<4;i++)                                    \
    _Pragma("unroll") for (int j=0;j<4;j++) acc[a][b][i][j]=0.f;

#define GEMM_MAINLOOP(Aload, Bload)                                            \
    for (int k0 = 0; k0 < K; k0 += 8){                                         \
        float4 av = (Aload);                                                   \
        float4 bv = (Bload);                                                   \
        As[lr*4+0][lrow]=av.x; As[lr*4+1][lrow]=av.y;                          \
        As[lr*4+2][lrow]=av.z; As[lr*4+3][lrow]=av.w;                          \
        Bs[lr*4+0][lrow]=bv.x; Bs[lr*4+1][lrow]=bv.y;                          \
        Bs[lr*4+2][lrow]=bv.z; Bs[lr*4+3][lrow]=bv.w;                          \
        __syncthreads();                                                       \
        _Pragma("unroll")                                                      \
        for (int kk = 0; kk < 8; kk++){                                        \
            float4 a0 = *(const float4*)&As[kk][wm + lm*4];                    \
            float4 a1 = *(const float4*)&As[kk][wm + 16 + lm*4];               \
            float4 b0 = *(const float4*)&Bs[kk][wn + ln*4];                    \
            float4 b1 = *(const float4*)&Bs[kk][wn + 32 + ln*4];               \
            float ar[2][4] = {{a0.x,a0.y,a0.z,a0.w},{a1.x,a1.y,a1.z,a1.w}};    \
            float br[2][4] = {{b0.x,b0.y,b0.z,b0.w},{b1.x,b1.y,b1.z,b1.w}};    \
            _Pragma("unroll") for (int ih=0;ih<2;ih++)                         \
            _Pragma("unroll") for (int i=0;i<4;i++)                            \
            _Pragma("unroll") for (int jh=0;jh<2;jh++)                         \
            _Pragma("unroll") for (int j=0;j<4;j++)                            \
                acc[ih][jh][i][j] += ar[ih][i]*br[jh][j];                      \
        }                                                                      \
        __syncthreads();                                                      \
    }

__global__ __launch_bounds__(256,2)
void gemm_nt_dense(const float* __restrict__ A,
                   const float* __restrict__ B,
                   float* __restrict__ C,
                   int M, int N, int K)
{
    const int m0 = blockIdx.y * 128, n0 = blockIdx.x * 128;
    GEMM_PROLOG();
    const int arow = m0 + lrow;
    const bool avalid = arow < M;
    const float* Aptr = A + (size_t)arow * K + lr*4;
    const float* Bptr = B + (size_t)(n0 + lrow) * K + lr*4;
    GEMM_MAINLOOP(avalid ? *(const float4*)(Aptr + k0) : make_float4(0,0,0,0),
                  *(const float4*)(Bptr + k0));
    #pragma unroll
    for (int ih = 0; ih < 2; ih++)
    #pragma unroll
    for (int i = 0; i < 4; i++){
        int row = m0 + wm + ih*16 + lm*4 + i;
        if (row < M){
            float* Crow = C + (size_t)row * N + n0;
            #pragma unroll
            for (int jh = 0; jh < 2; jh++){
                float4 v = make_float4(acc[ih][jh][i][0], acc[ih][jh][i][1],
                                       acc[ih][jh][i][2], acc[ih][jh][i][3]);
                *(float4*)(Crow + wn + jh*32 + ln*4) = v;
            }
        }
    }
}

// grouped: per-expert GEMM over dynamic token lists. gatherX=1 -> A rows are
// x[bucket[e][m]]; gatherX=0 -> A rows are X[offsets[e]+m] (compact).
__global__ __launch_bounds__(256,2)
void gemm_nt_grouped(const float* __restrict__ X,
                     const float* __restrict__ W,
                     float* __restrict__ C,
                     int N, int K, int gatherX)
{
    const int e   = blockIdx.z;
    const int cnt = g_counts[e];
    const int m0  = blockIdx.y * 128;
    if (m0 >= cnt) return;
    const int off = g_offsets[e];
    const float* B = W + (size_t)e * N * K;
    const int n0 = blockIdx.x * 128;
    GEMM_PROLOG();
    const int m = m0 + lrow;
    const bool avalid = m < cnt;
    size_t arow;
    if (gatherX) arow = avalid ? (size_t)g_bucket[e*CAP + m] : 0;
    else         arow = (size_t)(off + (avalid ? m : 0));
    const float* Aptr = X + arow * K + lr*4;
    const float* Bptr = B + (size_t)(n0 + lrow) * K + lr*4;
    GEMM_MAINLOOP(avalid ? *(const float4*)(Aptr + k0) : make_float4(0,0,0,0),
                  *(const float4*)(Bptr + k0));
    #pragma unroll
    for (int ih = 0; ih < 2; ih++)
    #pragma unroll
    for (int i = 0; i < 4; i++){
        int rloc = m0 + wm + ih*16 + lm*4 + i;
        if (rloc < cnt){
            float* Crow = C + (size_t)(off + rloc) * N + n0;
            #pragma unroll
            for (int jh = 0; jh < 2; jh++){
                float4 v = make_float4(acc[ih][jh][i][0], acc[ih][jh][i][1],
                                       acc[ih][jh][i][2], acc[ih][jh][i][3]);
                *(float4*)(Crow + wn + jh*32 + ln*4) = v;
            }
        }
    }
}

// ---------------- elementwise -------------------------------------------------
__global__ void silu_mul_shared_kernel(){
    size_t i = (size_t)blockIdx.x * blockDim.x + threadIdx.x;
    if (i < (size_t)T_TOK * ISH)
        g_smid[i] = silu_f(g_sg[i]) * g_su[i];
}

__global__ void silu_mul_grouped_kernel(){
    size_t i = (size_t)blockIdx.x * blockDim.x + threadIdx.x;
    if (i < (size_t)NPAIR * IDIM){
        size_t p = i / IDIM, c = i % IDIM;
        g_hmid[i] = silu_f(g_gu[p*2*IDIM + c]) * g_gu[p*2*IDIM + IDIM + c];
    }
}

// ---------------- combine: deterministic per-token sum of 6 expert rows ------
__global__ void combine_kernel(float* __restrict__ out){
    const int t = blockIdx.x;
    const int h = blockIdx.y * 256 + threadIdx.x;
    float acc = 0.f;
    #pragma unroll
    for (int k = 0; k < K_TOP; k++){
        int e    = g_topidx[t*K_TOP + k];
        float w  = g_topw [t*K_TOP + k];
        int row  = g_offsets[e] + g_slot[t*K_TOP + k];
        acc += w * g_y[(size_t)row * H_DIM + h];
    }
    out[(size_t)t * H_DIM + h] += acc;   // out already holds shared_out
}

// ---------------- launch ------------------------------------------------------
extern "C" void kernel_launch(void* const* d_in, const int* in_sizes, int n_in,
                              void* d_out, int out_size)
{
    const float* x    = (const float*)d_in[0];
    const float* rw   = (const float*)d_in[1];
    const float* bias = (const float*)d_in[2];
    const float* gup  = (const float*)d_in[3];
    const float* dwn  = (const float*)d_in[4];
    const float* sgw  = (const float*)d_in[5];
    const float* suw  = (const float*)d_in[6];
    const float* sdw  = (const float*)d_in[7];
    float* out = (float*)d_out;

    void *p_sg, *p_su, *p_smid, *p_gu, *p_hmid, *p_y;
    cudaGetSymbolAddress(&p_sg,   g_sg);
    cudaGetSymbolAddress(&p_su,   g_su);
    cudaGetSymbolAddress(&p_smid, g_smid);
    cudaGetSymbolAddress(&p_gu,   g_gu);
    cudaGetSymbolAddress(&p_hmid, g_hmid);
    cudaGetSymbolAddress(&p_y,    g_y);

    // routing
    zero_counts_kernel<<<1, 32>>>();
    router_kernel<<<T_TOK, 128>>>(x, rw, bias);
    scan_kernel<<<1, 32>>>();

    // shared expert: sg = x@Wg^T, su = x@Wu^T, smid = silu(sg)*su, out = smid@Wd^T
    gemm_nt_dense<<<dim3(ISH/128, T_TOK/128), 256>>>(x, sgw, (float*)p_sg,
                                                     T_TOK, ISH, H_DIM);
    gemm_nt_dense<<<dim3(ISH/128, T_TOK/128), 256>>>(x, suw, (float*)p_su,
                                                     T_TOK, ISH, H_DIM);
    {
        size_t n = (size_t)T_TOK * ISH;
        silu_mul_shared_kernel<<<(unsigned)((n + 255)/256), 256>>>();
    }
    gemm_nt_dense<<<dim3(H_DIM/128, T_TOK/128), 256>>>((float*)p_smid, sdw, out,
                                                       T_TOK, H_DIM, ISH);

    // grouped experts: gu = gather(x)@gate_up^T  (N = 2I = 1024)
    gemm_nt_grouped<<<dim3(2*IDIM/128, CAP/128, NE), 256>>>(
        x, gup, (float*)p_gu, 2*IDIM, H_DIM, 1);
    {
        size_t n = (size_t)NPAIR * IDIM;
        silu_mul_grouped_kernel<<<(unsigned)((n + 255)/256), 256>>>();
    }
    // y = hmid @ down^T  (N = H = 1024, K = I = 512)
    gemm_nt_grouped<<<dim3(H_DIM/128, CAP/128, NE), 256>>>(
        (float*)p_hmid, dwn, (float*)p_y, H_DIM, IDIM, 0);

    // deterministic combine
    combine_kernel<<<dim3(T_TOK, H_DIM/256), 256>>>(out);

    (void)in_sizes; (void)n_in; (void)out_size;
}

// round 5
// speedup vs baseline: 2.3738x; 2.3738x over previous
#include <cuda_runtime.h>
#include <cstdint>
#include <math.h>

#define T_TOK 2048
#define H_DIM 1024
#define NE    32
#define IDIM  512
#define K_TOP 6
#define ISH   1024
#define CAP   2048
#define NPAIR (T_TOK*K_TOP)   // 12288

// ---------------- scratch (static device globals; no runtime alloc) ----------
__device__ int   g_counts[NE];
__device__ int   g_offsets[NE];
__device__ int   g_bucket[NE*CAP];
__device__ int   g_topidx[NPAIR];
__device__ float g_topw[NPAIR];
__device__ int   g_slot[NPAIR];
__device__ float g_sg  [(size_t)T_TOK*ISH];
__device__ float g_su  [(size_t)T_TOK*ISH];
__device__ float g_smid[(size_t)T_TOK*ISH];
__device__ float g_gu  [(size_t)NPAIR*2*IDIM];
__device__ float g_hmid[(size_t)NPAIR*IDIM];
__device__ float g_y   [(size_t)NPAIR*H_DIM];

__device__ __forceinline__ float silu_f(float v){ return v / (1.f + __expf(-v)); }

__device__ __forceinline__ uint32_t smem_u32(const void* p){
    uint32_t a;
    asm("{ .reg .u64 t; cvta.to.shared.u64 t, %1; cvt.u32.u64 %0, t; }"
        : "=r"(a) : "l"(p));
    return a;
}

__device__ __forceinline__ void cpa16(uint32_t dst, const void* src, bool valid){
    asm volatile("cp.async.cg.shared.global [%0], [%1], 16, %2;"
                 :: "r"(dst), "l"(src), "r"(valid ? 16u : 0u) : "memory");
}
#define CPA_COMMIT() asm volatile("cp.async.commit_group;" ::: "memory")
#define CPA_WAIT1()  asm volatile("cp.async.wait_group 1;" ::: "memory")
#define CPA_WAIT0()  asm volatile("cp.async.wait_group 0;" ::: "memory")

// bf16 m16n8k16 mma, fp32 accumulate
__device__ __forceinline__ void mma16(float* c, const uint32_t* a, const uint32_t* b){
    asm volatile("mma.sync.aligned.m16n8k16.row.col.f32.bf16.bf16.f32 "
                 "{%0,%1,%2,%3}, {%4,%5,%6,%7}, {%8,%9}, {%0,%1,%2,%3};"
                 : "+f"(c[0]), "+f"(c[1]), "+f"(c[2]), "+f"(c[3])
                 : "r"(a[0]), "r"(a[1]), "r"(a[2]), "r"(a[3]),
                   "r"(b[0]), "r"(b[1]));
}

// split a float2 (consecutive k) into bf16x2 hi + bf16x2 lo (low half = first k)
__device__ __forceinline__ void split2(float2 f, uint32_t& hi, uint32_t& lo){
    asm("cvt.rn.bf16x2.f32 %0, %1, %2;" : "=r"(hi) : "f"(f.y), "f"(f.x));
    float h0 = __uint_as_float(hi << 16);
    float h1 = __uint_as_float(hi & 0xFFFF0000u);
    float l0 = f.x - h0, l1 = f.y - h1;
    asm("cvt.rn.bf16x2.f32 %0, %1, %2;" : "=r"(lo) : "f"(l1), "f"(l0));
}

// swizzled float2 load from a 32-float-wide smem tile
// store-side swizzle: col4 ^= (row&3)<<1  (16B units)  => float col ^= (row&3)<<3
__device__ __forceinline__ float2 lds2(const float* base, int row, int col){
    int idx = row*32 + (col ^ ((row & 3) << 3));
    return *(const float2*)(base + idx);
}

// ======================= 3xBF16 mma.sync GEMM ================================
// C[m,n] = sum_k A[m,k] * B[n,k]   (A, B both K-contiguous, fp32)
// CTA tile 128x128, BK=32, 256 threads = 8 warps (2 m x 4 n), warp tile 64x32.
// fp32 tiles in smem via cp.async (double-buffered); fragments split into
// bf16 hi/lo in registers; D = Ahi*Bhi + Ahi*Blo + Alo*Bhi (fp32 accum).
// MODE 0: dense; MODE 1: grouped gather via g_bucket; MODE 2: grouped compact.

#define GEMM_SMEM 65536  // 2 x (A 16KB + B 16KB)

template<int MODE>
__global__ __launch_bounds__(256)
void gemm_mma(const float* __restrict__ A, const float* __restrict__ W,
              float* __restrict__ C, int M, int N, int K)
{
    int e = 0, cnt = M, off = 0;
    const float* Wp = W;
    if (MODE){
        e = blockIdx.z;
        cnt = g_counts[e];
        if ((int)blockIdx.y * 128 >= cnt) return;
        off = g_offsets[e];
        Wp += (size_t)e * N * K;
    }
    const int m0 = blockIdx.y * 128, n0 = blockIdx.x * 128;

    extern __shared__ float smf[];   // A0 A1 B0 B1, 4096 floats each
    const uint32_t sb = smem_u32(smf);

    const int tid = threadIdx.x, warp = tid >> 5, lane = tid & 31;
    const int wm = (warp >> 2) * 64, wn = (warp & 3) * 32;
    const int r4 = lane >> 2, c2 = lane & 3;

    // global load setup: 4 rows per thread for each of A and B
    const int lr0 = tid >> 3, c4 = tid & 7;
    const float* ap[4]; const float* bp[4]; bool av[4]; uint32_t soj[4];
    #pragma unroll
    for (int j = 0; j < 4; j++){
        int r = lr0 + j*32;
        soj[j] = (uint32_t)(r*128 + ((c4 ^ ((r & 3) << 1)) << 4));
        int m = m0 + r;
        size_t garow;
        if (MODE == 0){ av[j] = true; garow = (size_t)m; }
        else if (MODE == 1){ av[j] = m < cnt; garow = av[j] ? (size_t)g_bucket[e*CAP + m] : 0; }
        else { av[j] = m < cnt; garow = (size_t)(off + (av[j] ? m : 0)); }
        ap[j] = A  + garow * (size_t)K + c4*4;
        bp[j] = Wp + (size_t)(n0 + r) * K + c4*4;
    }

    float acc[4][4][4];
    #pragma unroll
    for (int a = 0; a < 4; a++)
    #pragma unroll
    for (int b = 0; b < 4; b++)
    #pragma unroll
    for (int q = 0; q < 4; q++) acc[a][b][q] = 0.f;

    const int nk = K >> 5;

    // prologue: chunk 0 -> buf 0
    #pragma unroll
    for (int j = 0; j < 4; j++){
        cpa16(sb + soj[j],         ap[j], av[j]);
        cpa16(sb + 32768 + soj[j], bp[j], true);
    }
    CPA_COMMIT();

    for (int ch = 0; ch < nk; ch++){
        const int b = ch & 1;
        if (ch + 1 < nk){
            const uint32_t bo = (uint32_t)(((ch + 1) & 1) * 16384);
            const int ko = (ch + 1) << 5;
            #pragma unroll
            for (int j = 0; j < 4; j++){
                cpa16(sb + bo + soj[j],         ap[j] + ko, av[j]);
                cpa16(sb + 32768 + bo + soj[j], bp[j] + ko, true);
            }
            CPA_COMMIT();
            CPA_WAIT1();
        } else {
            CPA_WAIT0();
        }
        __syncthreads();

        const float* Ab = smf + b * 4096;
        const float* Bb = smf + 8192 + b * 4096;

        #pragma unroll
        for (int ks = 0; ks < 2; ks++){
            const int kb = ks * 16 + 2*c2;
            // B fragments for 4 n-tiles, split hi/lo
            uint32_t bhi[4][2], blo[4][2];
            #pragma unroll
            for (int nf = 0; nf < 4; nf++){
                const int nr = wn + nf*8 + r4;
                split2(lds2(Bb, nr, kb),     bhi[nf][0], blo[nf][0]);
                split2(lds2(Bb, nr, kb + 8), bhi[nf][1], blo[nf][1]);
            }
            #pragma unroll
            for (int mf = 0; mf < 4; mf++){
                const int mr = wm + mf*16 + r4;
                uint32_t ahi[4], alo[4];
                split2(lds2(Ab, mr,     kb),     ahi[0], alo[0]);
                split2(lds2(Ab, mr + 8, kb),     ahi[1], alo[1]);
                split2(lds2(Ab, mr,     kb + 8), ahi[2], alo[2]);
                split2(lds2(Ab, mr + 8, kb + 8), ahi[3], alo[3]);
                #pragma unroll
                for (int nf = 0; nf < 4; nf++){
                    mma16(acc[mf][nf], ahi, bhi[nf]);
                    mma16(acc[mf][nf], ahi, blo[nf]);
                    mma16(acc[mf][nf], alo, bhi[nf]);
                }
            }
        }
        __syncthreads();
    }

    // epilogue: c0,c1 at (row, col..col+1); c2,c3 at (row+8, col..col+1)
    #pragma unroll
    for (int mf = 0; mf < 4; mf++){
        const int rl = wm + mf*16 + r4;
        #pragma unroll
        for (int half = 0; half < 2; half++){
            const int rloc = rl + half*8;
            bool valid; size_t crow;
            if (MODE == 0){ valid = (m0 + rloc) < M; crow = (size_t)(m0 + rloc); }
            else { valid = rloc < (cnt - m0); crow = (size_t)(off + m0 + rloc); }
            if (valid){
                float* cp = C + crow * N + n0 + wn + c2*2;
                #pragma unroll
                for (int nf = 0; nf < 4; nf++){
                    float2 v;
                    v.x = acc[mf][nf][half*2 + 0];
                    v.y = acc[mf][nf][half*2 + 1];
                    *(float2*)(cp + nf*8) = v;
                }
            }
        }
    }
}

// ---------------- router: softmax + bias + top-6 + bucketing ----------------
__global__ void zero_counts_kernel(){
    if (threadIdx.x < NE) g_counts[threadIdx.x] = 0;
}

__global__ void router_kernel(const float* __restrict__ x,
                              const float* __restrict__ rw,
                              const float* __restrict__ bias)
{
    __shared__ float sx[H_DIM];
    __shared__ float slog[NE];
    const int t = blockIdx.x;
    const float* xr = x + (size_t)t * H_DIM;
    for (int i = threadIdx.x; i < H_DIM; i += blockDim.x) sx[i] = xr[i];
    __syncthreads();

    const int warp = threadIdx.x >> 5, lane = threadIdx.x & 31;
    for (int e = warp*8; e < warp*8 + 8; e++){
        const float* w = rw + (size_t)e * H_DIM;
        float s = 0.f;
        for (int h = lane; h < H_DIM; h += 32) s += sx[h] * w[h];
        #pragma unroll
        for (int o = 16; o; o >>= 1) s += __shfl_xor_sync(0xffffffffu, s, o);
        if (lane == 0) slog[e] = s;
    }
    __syncthreads();

    if (threadIdx.x == 0){
        float mx = -1e30f;
        for (int e = 0; e < NE; e++) mx = fmaxf(mx, slog[e]);
        float p[NE]; float sum = 0.f;
        for (int e = 0; e < NE; e++){ p[e] = expf(slog[e] - mx); sum += p[e]; }
        float inv = 1.f / sum;
        float corr[NE];
        for (int e = 0; e < NE; e++){ p[e] *= inv; corr[e] = p[e] + bias[e]; }

        int idx[K_TOP]; bool used[NE];
        for (int e = 0; e < NE; e++) used[e] = false;
        for (int k = 0; k < K_TOP; k++){
            int best = -1; float bv = -1e30f;
            for (int e = 0; e < NE; e++)
                if (!used[e] && corr[e] > bv){ bv = corr[e]; best = e; }
            used[best] = true; idx[k] = best;
        }
        float wsum = 0.f;
        for (int k = 0; k < K_TOP; k++) wsum += p[idx[k]];
        wsum = fmaxf(wsum, 1e-12f);
        for (int k = 0; k < K_TOP; k++){
            int e = idx[k];
            float wn = p[e] / wsum;
            int slot = atomicAdd(&g_counts[e], 1);
            g_bucket[e*CAP + slot] = t;
            g_topidx[t*K_TOP + k] = e;
            g_topw [t*K_TOP + k] = wn;
            g_slot [t*K_TOP + k] = slot;
        }
    }
}

__global__ void scan_kernel(){
    if (threadIdx.x == 0){
        int s = 0;
        for (int e = 0; e < NE; e++){ g_offsets[e] = s; s += g_counts[e]; }
    }
}

// ---------------- elementwise -------------------------------------------------
__global__ void silu_mul_shared_kernel(){
    size_t i = (size_t)blockIdx.x * blockDim.x + threadIdx.x;
    if (i < (size_t)T_TOK * ISH)
        g_smid[i] = silu_f(g_sg[i]) * g_su[i];
}

__global__ void silu_mul_grouped_kernel(){
    size_t i = (size_t)blockIdx.x * blockDim.x + threadIdx.x;
    if (i < (size_t)NPAIR * IDIM){
        size_t p = i / IDIM, c = i % IDIM;
        g_hmid[i] = silu_f(g_gu[p*2*IDIM + c]) * g_gu[p*2*IDIM + IDIM + c];
    }
}

// ---------------- combine: deterministic per-token sum of 6 expert rows ------
__global__ void combine_kernel(float* __restrict__ out){
    const int t = blockIdx.x;
    const int h = blockIdx.y * 256 + threadIdx.x;
    float acc = 0.f;
    #pragma unroll
    for (int k = 0; k < K_TOP; k++){
        int e    = g_topidx[t*K_TOP + k];
        float w  = g_topw [t*K_TOP + k];
        int row  = g_offsets[e] + g_slot[t*K_TOP + k];
        acc += w * g_y[(size_t)row * H_DIM + h];
    }
    out[(size_t)t * H_DIM + h] += acc;   // out already holds shared_out
}

// ---------------- launch ------------------------------------------------------
extern "C" void kernel_launch(void* const* d_in, const int* in_sizes, int n_in,
                              void* d_out, int out_size)
{
    const float* x    = (const float*)d_in[0];
    const float* rw   = (const float*)d_in[1];
    const float* bias = (const float*)d_in[2];
    const float* gup  = (const float*)d_in[3];
    const float* dwn  = (const float*)d_in[4];
    const float* sgw  = (const float*)d_in[5];
    const float* suw  = (const float*)d_in[6];
    const float* sdw  = (const float*)d_in[7];
    float* out = (float*)d_out;

    void *p_sg, *p_su, *p_smid, *p_gu, *p_hmid, *p_y;
    cudaGetSymbolAddress(&p_sg,   g_sg);
    cudaGetSymbolAddress(&p_su,   g_su);
    cudaGetSymbolAddress(&p_smid, g_smid);
    cudaGetSymbolAddress(&p_gu,   g_gu);
    cudaGetSymbolAddress(&p_hmid, g_hmid);
    cudaGetSymbolAddress(&p_y,    g_y);

    cudaFuncSetAttribute(gemm_mma<0>, cudaFuncAttributeMaxDynamicSharedMemorySize, GEMM_SMEM);
    cudaFuncSetAttribute(gemm_mma<1>, cudaFuncAttributeMaxDynamicSharedMemorySize, GEMM_SMEM);
    cudaFuncSetAttribute(gemm_mma<2>, cudaFuncAttributeMaxDynamicSharedMemorySize, GEMM_SMEM);

    // routing
    zero_counts_kernel<<<1, 32>>>();
    router_kernel<<<T_TOK, 128>>>(x, rw, bias);
    scan_kernel<<<1, 32>>>();

    // shared expert: sg = x@Wg^T, su = x@Wu^T, smid = silu(sg)*su, out = smid@Wd^T
    gemm_mma<0><<<dim3(ISH/128, T_TOK/128, 1), 256, GEMM_SMEM>>>(
        x, sgw, (float*)p_sg, T_TOK, ISH, H_DIM);
    gemm_mma<0><<<dim3(ISH/128, T_TOK/128, 1), 256, GEMM_SMEM>>>(
        x, suw, (float*)p_su, T_TOK, ISH, H_DIM);
    {
        size_t n = (size_t)T_TOK * ISH;
        silu_mul_shared_kernel<<<(unsigned)((n + 255)/256), 256>>>();
    }
    gemm_mma<0><<<dim3(H_DIM/128, T_TOK/128, 1), 256, GEMM_SMEM>>>(
        (float*)p_smid, sdw, out, T_TOK, H_DIM, ISH);

    // grouped experts: gu = gather(x)@gate_up^T  (N = 2I = 1024, K = H)
    gemm_mma<1><<<dim3(2*IDIM/128, CAP/128, NE), 256, GEMM_SMEM>>>(
        x, gup, (float*)p_gu, CAP, 2*IDIM, H_DIM);
    {
        size_t n = (size_t)NPAIR * IDIM;
        silu_mul_grouped_kernel<<<(unsigned)((n + 255)/256), 256>>>();
    }
    // y = hmid @ down^T  (N = H, K = I = 512)
    gemm_mma<2><<<dim3(H_DIM/128, CAP/128, NE), 256, GEMM_SMEM>>>(
        (float*)p_hmid, dwn, (float*)p_y, CAP, H_DIM, IDIM);

    // deterministic combine
    combine_kernel<<<dim3(T_TOK, H_DIM/256), 256>>>(out);

    (void)in_sizes; (void)n_in; (void)out_size;
}